// round 1
// baseline (speedup 1.0000x reference)
#include <cuda_runtime.h>

#define Bsz 4
#define Cch 256
#define Hh  64
#define Ww  64
#define Oo  256
#define Kt  9          // 3x3 taps
#define Md  (Bsz*Hh*Ww)   // 16384 pixels
#define Kd  (Cch*Kt)      // 2304 reduction dim

// ---------------- scratch (__device__ globals; no allocation) ----------------
__device__ float g_nhwc[(size_t)Bsz*Hh*Ww*Cch];   // 16.8 MB
__device__ float g_off[(size_t)Bsz*18*Hh*Ww];     // 1.2 MB
__device__ float g_A[(size_t)Md*Kd];              // 151 MB im2col of sampled values
__device__ float g_Bt[(size_t)Kd*Oo];             // 2.4 MB  Bt[k*256+c][o] = W[o][c][k]*inv[o]
__device__ float g_bias2[Oo];

// ---------------- 1) NCHW -> NHWC transpose ----------------
__global__ void k_transpose(const float* __restrict__ in) {
    __shared__ float t[32][33];
    int x0 = blockIdx.x * 32;
    int c0 = blockIdx.y * 32;
    int bh = blockIdx.z;
    int b = bh >> 6, y = bh & 63;
    #pragma unroll
    for (int i = threadIdx.y; i < 32; i += 8)
        t[i][threadIdx.x] = in[(((size_t)(b*Cch + c0 + i)*Hh + y)*Ww) + x0 + threadIdx.x];
    __syncthreads();
    #pragma unroll
    for (int i = threadIdx.y; i < 32; i += 8)
        g_nhwc[(((size_t)(b*Hh + y)*Ww + x0 + i) << 8) + c0 + threadIdx.x] = t[threadIdx.x][i];
}

// ---------------- 2) offset conv (18 channels, 3x3, pad 1) ----------------
#define OC_CH 16
__global__ __launch_bounds__(256) void k_offset_conv(const float* __restrict__ in,
                                                     const float* __restrict__ w_off,
                                                     const float* __restrict__ b_off) {
    int bid = blockIdx.x;          // b*64 + y
    int b = bid >> 6, y = bid & 63;
    int tid = threadIdx.x;
    int x  = tid & 63;
    int jj = tid >> 6;             // 0..3
    __shared__ float sin_[3][OC_CH][66];     // rows y-1..y+1, channels chunk, x -1..64
    __shared__ float ws[18][OC_CH][9];
    float acc[5] = {0.f, 0.f, 0.f, 0.f, 0.f};

    for (int c0 = 0; c0 < Cch; c0 += OC_CH) {
        for (int idx = tid; idx < 3*OC_CH*66; idx += 256) {
            int r  = idx / (OC_CH*66);
            int rem = idx - r*(OC_CH*66);
            int cc = rem / 66;
            int xx = rem - cc*66;
            int gy = y - 1 + r;
            int gx = xx - 1;
            float v = 0.f;
            if ((unsigned)gy < 64u && (unsigned)gx < 64u)
                v = in[(((size_t)(b*Cch + c0 + cc)*Hh + gy)*Ww) + gx];
            sin_[r][cc][xx] = v;
        }
        for (int idx = tid; idx < 18*OC_CH*9; idx += 256) {
            int j  = idx / (OC_CH*9);
            int rem = idx - j*(OC_CH*9);
            int cc = rem / 9;
            int p  = rem - cc*9;
            ws[j][cc][p] = w_off[((size_t)(j*Cch + c0 + cc))*9 + p];
        }
        __syncthreads();
        for (int cc = 0; cc < OC_CH; cc++) {
            #pragma unroll
            for (int i = 0; i < 3; i++) {
                #pragma unroll
                for (int jx = 0; jx < 3; jx++) {
                    float v = sin_[i][cc][x + jx];
                    int p = i*3 + jx;
                    #pragma unroll
                    for (int t = 0; t < 5; t++) {
                        int j = jj + (t << 2);
                        if (j < 18) acc[t] += v * ws[j][cc][p];
                    }
                }
            }
        }
        __syncthreads();
    }
    #pragma unroll
    for (int t = 0; t < 5; t++) {
        int j = jj + (t << 2);
        if (j < 18)
            g_off[(((size_t)(b*18 + j)*Hh + y)*Ww) + x] = acc[t] + b_off[j];
    }
}

// ---------------- 3) bilinear sample -> im2col A ----------------
__global__ __launch_bounds__(64) void k_sample() {
    int m = blockIdx.x;                       // pixel index
    int b = m >> 12, y = (m >> 6) & 63, x = m & 63;
    int c = threadIdx.x * 4;

    for (int k = 0; k < Kt; k++) {
        float dy = g_off[(((size_t)(b*18 + 2*k    )*Hh + y)*Ww) + x];
        float dx = g_off[(((size_t)(b*18 + 2*k + 1)*Hh + y)*Ww) + x];
        float py = (float)(y - 1 + (k/3)) + dy;
        float px = (float)(x - 1 + (k%3)) + dx;
        float y0f = floorf(py), x0f = floorf(px);
        float ly = py - y0f, lx = px - x0f;
        int y0 = (int)y0f, x0i = (int)x0f;
        int y1 = y0 + 1,  x1 = x0i + 1;
        float vy0 = (y0  >= 0 && y0  < 64) ? 1.f : 0.f;
        float vy1 = (y1  >= 0 && y1  < 64) ? 1.f : 0.f;
        float vx0 = (x0i >= 0 && x0i < 64) ? 1.f : 0.f;
        float vx1 = (x1  >= 0 && x1  < 64) ? 1.f : 0.f;
        float w00 = (1.f-ly)*(1.f-lx)*vy0*vx0;
        float w01 = (1.f-ly)*lx      *vy0*vx1;
        float w10 = ly      *(1.f-lx)*vy1*vx0;
        float w11 = ly      *lx      *vy1*vx1;
        int y0c = min(max(y0, 0), 63), y1c = min(max(y1, 0), 63);
        int x0c = min(max(x0i,0), 63), x1c = min(max(x1, 0), 63);
        const float* p00 = g_nhwc + (((size_t)(b*Hh + y0c)*Ww + x0c) << 8);
        const float* p01 = g_nhwc + (((size_t)(b*Hh + y0c)*Ww + x1c) << 8);
        const float* p10 = g_nhwc + (((size_t)(b*Hh + y1c)*Ww + x0c) << 8);
        const float* p11 = g_nhwc + (((size_t)(b*Hh + y1c)*Ww + x1c) << 8);
        float4 a00 = *(const float4*)(p00 + c);
        float4 a01 = *(const float4*)(p01 + c);
        float4 a10 = *(const float4*)(p10 + c);
        float4 a11 = *(const float4*)(p11 + c);
        float4 r;
        r.x = w00*a00.x + w01*a01.x + w10*a10.x + w11*a11.x;
        r.y = w00*a00.y + w01*a01.y + w10*a10.y + w11*a11.y;
        r.z = w00*a00.z + w01*a01.z + w10*a10.z + w11*a11.z;
        r.w = w00*a00.w + w01*a01.w + w10*a10.w + w11*a11.w;
        *(float4*)(g_A + (size_t)m*Kd + k*Cch + c) = r;
    }
}

// ---------------- 4) weight prep: fold BN, transpose to [kd][o] ----------------
__global__ void k_prep_weight(const float* __restrict__ w,
                              const float* __restrict__ bias,
                              const float* __restrict__ gamma,
                              const float* __restrict__ beta,
                              const float* __restrict__ mean,
                              const float* __restrict__ var) {
    int kd = blockIdx.x;           // k*256 + c
    int k = kd >> 8;
    int c = kd & 255;
    int o = threadIdx.x;
    float inv = gamma[o] * rsqrtf(var[o] + 1e-5f);
    g_Bt[(size_t)kd*Oo + o] = w[((size_t)(o*Cch + c))*9 + k] * inv;
    if (kd == 0)
        g_bias2[o] = bias[o]*inv + beta[o] - mean[o]*inv;
}

// ---------------- 5) GEMM: out[m][o] = A[m][:] . Bt[:][o], + bias, relu ----------------
#define BM 128
#define BN 64
#define BK 16
__global__ __launch_bounds__(256) void k_gemm(float* __restrict__ out) {
    __shared__ float As[BK][BM + 4];   // transposed store, padded
    __shared__ float Bs[BK][BN];
    int tid = threadIdx.x;
    int n0 = blockIdx.x * BN;
    int m0 = blockIdx.y * BM;
    int tx = tid & 15;     // n dir: 16*4 = 64
    int ty = tid >> 4;     // m dir: 16*8 = 128

    float acc[8][4];
    #pragma unroll
    for (int i = 0; i < 8; i++)
        #pragma unroll
        for (int j = 0; j < 4; j++) acc[i][j] = 0.f;

    float bv[4];
    #pragma unroll
    for (int j = 0; j < 4; j++) bv[j] = g_bias2[n0 + tx*4 + j];

    for (int kd0 = 0; kd0 < Kd; kd0 += BK) {
        // A tile: 128 rows x 16, 512 float4
        #pragma unroll
        for (int q = 0; q < 2; q++) {
            int fi = q*256 + tid;
            int row = fi >> 2;
            int c4  = fi & 3;
            float4 v = *(const float4*)(g_A + (size_t)(m0 + row)*Kd + kd0 + c4*4);
            As[c4*4 + 0][row] = v.x;
            As[c4*4 + 1][row] = v.y;
            As[c4*4 + 2][row] = v.z;
            As[c4*4 + 3][row] = v.w;
        }
        // B tile: 16 rows x 64, 256 float4
        {
            int kk  = tid >> 4;
            int c4  = tid & 15;
            float4 v = *(const float4*)(g_Bt + (size_t)(kd0 + kk)*Oo + n0 + c4*4);
            *(float4*)&Bs[kk][c4*4] = v;
        }
        __syncthreads();
        #pragma unroll
        for (int kk = 0; kk < BK; kk++) {
            float4 a0 = *(const float4*)&As[kk][ty*8];
            float4 a1 = *(const float4*)&As[kk][ty*8 + 4];
            float4 bb = *(const float4*)&Bs[kk][tx*4];
            float av[8] = {a0.x, a0.y, a0.z, a0.w, a1.x, a1.y, a1.z, a1.w};
            float bw[4] = {bb.x, bb.y, bb.z, bb.w};
            #pragma unroll
            for (int i = 0; i < 8; i++)
                #pragma unroll
                for (int j = 0; j < 4; j++)
                    acc[i][j] += av[i] * bw[j];
        }
        __syncthreads();
    }

    #pragma unroll
    for (int i = 0; i < 8; i++) {
        int m = m0 + ty*8 + i;
        int b = m >> 12, y = (m >> 6) & 63, xx = m & 63;
        #pragma unroll
        for (int j = 0; j < 4; j++) {
            int o = n0 + tx*4 + j;
            float v = acc[i][j] + bv[j];
            out[(((size_t)((b << 8) + o)*Hh + y)*Ww) + xx] = fmaxf(v, 0.f);
        }
    }
}

// ---------------- launch ----------------
extern "C" void kernel_launch(void* const* d_in, const int* in_sizes, int n_in,
                              void* d_out, int out_size) {
    const float* input  = (const float*)d_in[0];
    const float* w_off  = (const float*)d_in[1];
    const float* b_off  = (const float*)d_in[2];
    const float* weight = (const float*)d_in[3];
    const float* bias   = (const float*)d_in[4];
    const float* gamma  = (const float*)d_in[5];
    const float* beta   = (const float*)d_in[6];
    const float* mean   = (const float*)d_in[7];
    const float* var    = (const float*)d_in[8];
    float* out = (float*)d_out;

    k_transpose<<<dim3(2, 8, Bsz*Hh), dim3(32, 8)>>>(input);
    k_offset_conv<<<Bsz*Hh, 256>>>(input, w_off, b_off);
    k_sample<<<Md, 64>>>();
    k_prep_weight<<<Kd, Oo>>>(weight, bias, gamma, beta, mean, var);
    k_gemm<<<dim3(Oo/BN, Md/BM), 256>>>(out);
}

// round 3
// speedup vs baseline: 1.7663x; 1.7663x over previous
#include <cuda_runtime.h>
#include <cuda_bf16.h>
#include <cstdint>

#define Bsz 4
#define Cch 256
#define Hh  64
#define Ww  64
#define Oo  256
#define Kt  9
#define Md  (Bsz*Hh*Ww)   // 16384
#define Kd  (Cch*Kt)      // 2304

// ---------------- scratch ----------------
__device__ float g_nhwc[(size_t)Bsz*Hh*Ww*Cch];
__device__ float g_off[(size_t)Bsz*18*Hh*Ww];
__device__ __nv_bfloat16 g_Ah[(size_t)Md*Kd];
__device__ __nv_bfloat16 g_Al[(size_t)Md*Kd];
__device__ __nv_bfloat16 g_Bh[(size_t)Oo*Kd];
__device__ __nv_bfloat16 g_Bl[(size_t)Oo*Kd];
__device__ float g_bias2[Oo];

// ---------------- helpers ----------------
__device__ __forceinline__ uint32_t smem_u32(const void* p) {
    uint32_t a;
    asm("{ .reg .u64 t; cvta.to.shared.u64 t, %1; cvt.u32.u64 %0, t; }" : "=r"(a) : "l"(p));
    return a;
}
__device__ __forceinline__ void cpa16(uint32_t s, const void* g) {
    asm volatile("cp.async.cg.shared.global [%0], [%1], 16;" :: "r"(s), "l"(g));
}
#define LDMX4(r, addr) \
    asm volatile("ldmatrix.sync.aligned.m8n8.x4.shared.b16 {%0,%1,%2,%3}, [%4];" \
        : "=r"((r)[0]), "=r"((r)[1]), "=r"((r)[2]), "=r"((r)[3]) : "r"(addr))
#define MMA16816(d, a, b0, b1) \
    asm volatile("mma.sync.aligned.m16n8k16.row.col.f32.bf16.bf16.f32 " \
        "{%0,%1,%2,%3}, {%4,%5,%6,%7}, {%8,%9}, {%0,%1,%2,%3};" \
        : "+f"((d)[0]), "+f"((d)[1]), "+f"((d)[2]), "+f"((d)[3]) \
        : "r"((a)[0]), "r"((a)[1]), "r"((a)[2]), "r"((a)[3]), "r"(b0), "r"(b1))

// ---------------- 1) NCHW -> NHWC ----------------
__global__ void k_transpose(const float* __restrict__ in) {
    __shared__ float t[32][33];
    int x0 = blockIdx.x * 32;
    int c0 = blockIdx.y * 32;
    int bh = blockIdx.z;
    int b = bh >> 6, y = bh & 63;
    #pragma unroll
    for (int i = threadIdx.y; i < 32; i += 8)
        t[i][threadIdx.x] = in[(((size_t)(b*Cch + c0 + i)*Hh + y)*Ww) + x0 + threadIdx.x];
    __syncthreads();
    #pragma unroll
    for (int i = threadIdx.y; i < 32; i += 8)
        g_nhwc[(((size_t)(b*Hh + y)*Ww + x0 + i) << 8) + c0 + threadIdx.x] = t[threadIdx.x][i];
}

// ---------------- 2) offset conv ----------------
#define OC_CH 16
__global__ __launch_bounds__(256) void k_offset_conv(const float* __restrict__ in,
                                                     const float* __restrict__ w_off,
                                                     const float* __restrict__ b_off) {
    int bid = blockIdx.x;
    int b = bid >> 6, y = bid & 63;
    int tid = threadIdx.x;
    int x  = tid & 63;
    int jj = tid >> 6;
    __shared__ float sin_[3][OC_CH][66];
    __shared__ float ws[18][OC_CH][9];
    float acc[5] = {0.f, 0.f, 0.f, 0.f, 0.f};

    for (int c0 = 0; c0 < Cch; c0 += OC_CH) {
        for (int idx = tid; idx < 3*OC_CH*66; idx += 256) {
            int r  = idx / (OC_CH*66);
            int rem = idx - r*(OC_CH*66);
            int cc = rem / 66;
            int xx = rem - cc*66;
            int gy = y - 1 + r;
            int gx = xx - 1;
            float v = 0.f;
            if ((unsigned)gy < 64u && (unsigned)gx < 64u)
                v = in[(((size_t)(b*Cch + c0 + cc)*Hh + gy)*Ww) + gx];
            sin_[r][cc][xx] = v;
        }
        for (int idx = tid; idx < 18*OC_CH*9; idx += 256) {
            int j  = idx / (OC_CH*9);
            int rem = idx - j*(OC_CH*9);
            int cc = rem / 9;
            int p  = rem - cc*9;
            ws[j][cc][p] = w_off[((size_t)(j*Cch + c0 + cc))*9 + p];
        }
        __syncthreads();
        for (int cc = 0; cc < OC_CH; cc++) {
            #pragma unroll
            for (int i = 0; i < 3; i++) {
                #pragma unroll
                for (int jx = 0; jx < 3; jx++) {
                    float v = sin_[i][cc][x + jx];
                    int p = i*3 + jx;
                    #pragma unroll
                    for (int t = 0; t < 5; t++) {
                        int j = jj + (t << 2);
                        if (j < 18) acc[t] += v * ws[j][cc][p];
                    }
                }
            }
        }
        __syncthreads();
    }
    #pragma unroll
    for (int t = 0; t < 5; t++) {
        int j = jj + (t << 2);
        if (j < 18)
            g_off[(((size_t)(b*18 + j)*Hh + y)*Ww) + x] = acc[t] + b_off[j];
    }
}

// ---------------- 3) bilinear sample -> bf16 hi/lo im2col ----------------
__global__ __launch_bounds__(64) void k_sample() {
    int m = blockIdx.x;
    int b = m >> 12, y = (m >> 6) & 63, x = m & 63;
    int c = threadIdx.x * 4;

    for (int k = 0; k < Kt; k++) {
        float dy = g_off[(((size_t)(b*18 + 2*k    )*Hh + y)*Ww) + x];
        float dx = g_off[(((size_t)(b*18 + 2*k + 1)*Hh + y)*Ww) + x];
        float py = (float)(y - 1 + (k/3)) + dy;
        float px = (float)(x - 1 + (k%3)) + dx;
        float y0f = floorf(py), x0f = floorf(px);
        float ly = py - y0f, lx = px - x0f;
        int y0 = (int)y0f, x0i = (int)x0f;
        int y1 = y0 + 1,  x1 = x0i + 1;
        float vy0 = (y0  >= 0 && y0  < 64) ? 1.f : 0.f;
        float vy1 = (y1  >= 0 && y1  < 64) ? 1.f : 0.f;
        float vx0 = (x0i >= 0 && x0i < 64) ? 1.f : 0.f;
        float vx1 = (x1  >= 0 && x1  < 64) ? 1.f : 0.f;
        float w00 = (1.f-ly)*(1.f-lx)*vy0*vx0;
        float w01 = (1.f-ly)*lx      *vy0*vx1;
        float w10 = ly      *(1.f-lx)*vy1*vx0;
        float w11 = ly      *lx      *vy1*vx1;
        int y0c = min(max(y0, 0), 63), y1c = min(max(y1, 0), 63);
        int x0c = min(max(x0i,0), 63), x1c = min(max(x1, 0), 63);
        const float* p00 = g_nhwc + (((size_t)(b*Hh + y0c)*Ww + x0c) << 8);
        const float* p01 = g_nhwc + (((size_t)(b*Hh + y0c)*Ww + x1c) << 8);
        const float* p10 = g_nhwc + (((size_t)(b*Hh + y1c)*Ww + x0c) << 8);
        const float* p11 = g_nhwc + (((size_t)(b*Hh + y1c)*Ww + x1c) << 8);
        float4 a00 = *(const float4*)(p00 + c);
        float4 a01 = *(const float4*)(p01 + c);
        float4 a10 = *(const float4*)(p10 + c);
        float4 a11 = *(const float4*)(p11 + c);
        float4 r;
        r.x = w00*a00.x + w01*a01.x + w10*a10.x + w11*a11.x;
        r.y = w00*a00.y + w01*a01.y + w10*a10.y + w11*a11.y;
        r.z = w00*a00.z + w01*a01.z + w10*a10.z + w11*a11.z;
        r.w = w00*a00.w + w01*a01.w + w10*a10.w + w11*a11.w;

        __nv_bfloat162 h01, h23, l01, l23;
        h01.x = __float2bfloat16_rn(r.x); h01.y = __float2bfloat16_rn(r.y);
        h23.x = __float2bfloat16_rn(r.z); h23.y = __float2bfloat16_rn(r.w);
        l01.x = __float2bfloat16_rn(r.x - __bfloat162float(h01.x));
        l01.y = __float2bfloat16_rn(r.y - __bfloat162float(h01.y));
        l23.x = __float2bfloat16_rn(r.z - __bfloat162float(h23.x));
        l23.y = __float2bfloat16_rn(r.w - __bfloat162float(h23.y));
        size_t off = (size_t)m*Kd + k*Cch + c;
        *(__nv_bfloat162*)(g_Ah + off)     = h01;
        *(__nv_bfloat162*)(g_Ah + off + 2) = h23;
        *(__nv_bfloat162*)(g_Al + off)     = l01;
        *(__nv_bfloat162*)(g_Al + off + 2) = l23;
    }
}

// ---------------- 4) weight prep ----------------
__global__ __launch_bounds__(256) void k_prep_weight(const float* __restrict__ w,
                              const float* __restrict__ bias,
                              const float* __restrict__ gamma,
                              const float* __restrict__ beta,
                              const float* __restrict__ mean,
                              const float* __restrict__ var) {
    int o = blockIdx.x;
    int t = threadIdx.x;
    float inv = gamma[o] * rsqrtf(var[o] + 1e-5f);
    for (int kd = t; kd < Kd; kd += 256) {
        int tap = kd >> 8, c = kd & 255;
        float v = w[((size_t)(o*Cch + c))*9 + tap] * inv;
        __nv_bfloat16 hi = __float2bfloat16_rn(v);
        __nv_bfloat16 lo = __float2bfloat16_rn(v - __bfloat162float(hi));
        g_Bh[(size_t)o*Kd + kd] = hi;
        g_Bl[(size_t)o*Kd + kd] = lo;
    }
    if (t == 0)
        g_bias2[o] = bias[o]*inv + beta[o] - mean[o]*inv;
}

// ---------------- 5) bf16 mma.sync GEMM, 3-term hi/lo ----------------
// BM=128, BN=128, KC=32; smem per stage: Ah/Al/Bh/Bl each 128 rows x 40 bf16 (80B rows)
#define KC 32
#define NCH (Kd/KC)          // 72
#define PLN 10240            // bytes per plane (128*80)
#define STG 40960            // 4 planes

__global__ __launch_bounds__(256) void k_gemm_mma(float* __restrict__ out) {
    extern __shared__ char dsm[];
    const uint32_t sbase = smem_u32(dsm);
    const int tid = threadIdx.x, lid = tid & 31, wid = tid >> 5;
    const int warpM = wid & 3, warpN = wid >> 2;
    const int m0 = blockIdx.x * 128;
    const int n0 = blockIdx.y * 128;

    float acc[2][8][4];
    #pragma unroll
    for (int mt = 0; mt < 2; mt++)
        #pragma unroll
        for (int nt = 0; nt < 8; nt++)
            #pragma unroll
            for (int j = 0; j < 4; j++) acc[mt][nt][j] = 0.f;

    // ldmatrix per-thread offsets (within a plane)
    const uint32_t a_off = (uint32_t)((warpM*32 + (lid & 7) + ((lid >> 3) & 1)*8) * 80
                                      + (lid >> 4) * 16);
    const uint32_t b_off = (uint32_t)((warpN*64 + (lid & 7) + ((lid >> 4) & 1)*8) * 80
                                      + ((lid >> 3) & 1) * 16);

    // cp.async per-thread assignment: 2 iters, each covers (row, 16B-chunk j)
    const int r0 = tid >> 2,      j0 = tid & 3;
    const int r1 = (tid + 256) >> 2, j1 = (tid + 256) & 3;

    auto load = [&](int c, int p) {
        uint32_t sb = sbase + p * STG;
        size_t kOff = (size_t)c * KC;
        {
            uint32_t d = sb + r0*80 + j0*16;
            const char* a = (const char*)(g_Ah + (size_t)(m0 + r0)*Kd + kOff) + j0*16;
            const char* al = (const char*)(g_Al + (size_t)(m0 + r0)*Kd + kOff) + j0*16;
            const char* bh = (const char*)(g_Bh + (size_t)(n0 + r0)*Kd + kOff) + j0*16;
            const char* bl = (const char*)(g_Bl + (size_t)(n0 + r0)*Kd + kOff) + j0*16;
            cpa16(d,           a);
            cpa16(d + PLN,     al);
            cpa16(d + 2*PLN,   bh);
            cpa16(d + 3*PLN,   bl);
        }
        {
            uint32_t d = sb + r1*80 + j1*16;
            const char* a = (const char*)(g_Ah + (size_t)(m0 + r1)*Kd + kOff) + j1*16;
            const char* al = (const char*)(g_Al + (size_t)(m0 + r1)*Kd + kOff) + j1*16;
            const char* bh = (const char*)(g_Bh + (size_t)(n0 + r1)*Kd + kOff) + j1*16;
            const char* bl = (const char*)(g_Bl + (size_t)(n0 + r1)*Kd + kOff) + j1*16;
            cpa16(d,           a);
            cpa16(d + PLN,     al);
            cpa16(d + 2*PLN,   bh);
            cpa16(d + 3*PLN,   bl);
        }
        asm volatile("cp.async.commit_group;");
    };

    load(0, 0);

    for (int c = 0; c < NCH; c++) {
        int p = c & 1;
        if (c + 1 < NCH) {
            load(c + 1, 1 - p);
            asm volatile("cp.async.wait_group 1;" ::: "memory");
        } else {
            asm volatile("cp.async.wait_group 0;" ::: "memory");
        }
        __syncthreads();

        uint32_t sb = sbase + p * STG;
        #pragma unroll
        for (int kh = 0; kh < 2; kh++) {
            uint32_t ah[2][4], al[2][4];
            #pragma unroll
            for (int mt = 0; mt < 2; mt++) {
                uint32_t addr = sb + a_off + mt*(16*80) + kh*32;
                LDMX4(ah[mt], addr);
                LDMX4(al[mt], addr + PLN);
            }
            #pragma unroll
            for (int tp = 0; tp < 4; tp++) {
                uint32_t bh[4], bl[4];
                uint32_t baddr = sb + 2*PLN + b_off + tp*(16*80) + kh*32;
                LDMX4(bh, baddr);
                LDMX4(bl, baddr + PLN);
                #pragma unroll
                for (int q = 0; q < 2; q++) {
                    int nt = tp*2 + q;
                    #pragma unroll
                    for (int mt = 0; mt < 2; mt++) {
                        MMA16816(acc[mt][nt], ah[mt], bh[2*q], bh[2*q+1]);
                        MMA16816(acc[mt][nt], ah[mt], bl[2*q], bl[2*q+1]);
                        MMA16816(acc[mt][nt], al[mt], bh[2*q], bh[2*q+1]);
                    }
                }
            }
        }
        __syncthreads();
    }

    // epilogue: bias + relu, NCHW stores
    #pragma unroll
    for (int mt = 0; mt < 2; mt++) {
        int mA = m0 + warpM*32 + mt*16 + (lid >> 2);
        int mB = mA + 8;
        int bA = mA >> 12, bB = mB >> 12;
        int pA = mA & 4095, pB = mB & 4095;
        #pragma unroll
        for (int nt = 0; nt < 8; nt++) {
            int o = n0 + warpN*64 + nt*8 + (lid & 3)*2;
            float bv0 = g_bias2[o], bv1 = g_bias2[o + 1];
            float* d = acc[mt][nt];
            out[((size_t)bA << 20) + ((size_t)o << 12)       + pA] = fmaxf(d[0] + bv0, 0.f);
            out[((size_t)bA << 20) + ((size_t)(o+1) << 12)   + pA] = fmaxf(d[1] + bv1, 0.f);
            out[((size_t)bB << 20) + ((size_t)o << 12)       + pB] = fmaxf(d[2] + bv0, 0.f);
            out[((size_t)bB << 20) + ((size_t)(o+1) << 12)   + pB] = fmaxf(d[3] + bv1, 0.f);
        }
    }
}

// ---------------- launch ----------------
extern "C" void kernel_launch(void* const* d_in, const int* in_sizes, int n_in,
                              void* d_out, int out_size) {
    const float* input  = (const float*)d_in[0];
    const float* w_off  = (const float*)d_in[1];
    const float* b_off  = (const float*)d_in[2];
    const float* weight = (const float*)d_in[3];
    const float* bias   = (const float*)d_in[4];
    const float* gamma  = (const float*)d_in[5];
    const float* beta   = (const float*)d_in[6];
    const float* mean   = (const float*)d_in[7];
    const float* var    = (const float*)d_in[8];
    float* out = (float*)d_out;

    cudaFuncSetAttribute(k_gemm_mma, cudaFuncAttributeMaxDynamicSharedMemorySize, 2*STG);

    k_transpose<<<dim3(2, 8, Bsz*Hh), dim3(32, 8)>>>(input);
    k_offset_conv<<<Bsz*Hh, 256>>>(input, w_off, b_off);
    k_sample<<<Md, 64>>>();
    k_prep_weight<<<Oo, 256>>>(weight, bias, gamma, beta, mean, var);
    k_gemm_mma<<<dim3(Md/128, Oo/128), 256, 2*STG>>>(out);
}

// round 4
// speedup vs baseline: 1.8743x; 1.0611x over previous
#include <cuda_runtime.h>
#include <cuda_bf16.h>
#include <cstdint>

#define Bsz 4
#define Cch 256
#define Hh  64
#define Ww  64
#define Oo  256
#define Kt  9
#define Md  (Bsz*Hh*Ww)   // 16384
#define Kd  (Cch*Kt)      // 2304

// ---------------- scratch ----------------
__device__ float g_nhwc[(size_t)Bsz*Hh*Ww*Cch];
__device__ float g_off[(size_t)Bsz*18*Hh*Ww];
__device__ __nv_bfloat16 g_Ah[(size_t)Md*Kd];
__device__ __nv_bfloat16 g_Al[(size_t)Md*Kd];
__device__ __nv_bfloat16 g_Bh[(size_t)Oo*Kd];
__device__ __nv_bfloat16 g_Bl[(size_t)Oo*Kd];
__device__ float g_bias2[Oo];

// ---------------- helpers ----------------
__device__ __forceinline__ uint32_t smem_u32(const void* p) {
    uint32_t a;
    asm("{ .reg .u64 t; cvta.to.shared.u64 t, %1; cvt.u32.u64 %0, t; }" : "=r"(a) : "l"(p));
    return a;
}
__device__ __forceinline__ void cpa16(uint32_t s, const void* g) {
    asm volatile("cp.async.cg.shared.global [%0], [%1], 16;" :: "r"(s), "l"(g));
}
#define LDMX4(r, addr) \
    asm volatile("ldmatrix.sync.aligned.m8n8.x4.shared.b16 {%0,%1,%2,%3}, [%4];" \
        : "=r"((r)[0]), "=r"((r)[1]), "=r"((r)[2]), "=r"((r)[3]) : "r"(addr))
#define MMA16816(d, a, b0, b1) \
    asm volatile("mma.sync.aligned.m16n8k16.row.col.f32.bf16.bf16.f32 " \
        "{%0,%1,%2,%3}, {%4,%5,%6,%7}, {%8,%9}, {%0,%1,%2,%3};" \
        : "+f"((d)[0]), "+f"((d)[1]), "+f"((d)[2]), "+f"((d)[3]) \
        : "r"((a)[0]), "r"((a)[1]), "r"((a)[2]), "r"((a)[3]), "r"(b0), "r"(b1))

// ---------------- 1) NCHW -> NHWC ----------------
__global__ void k_transpose(const float* __restrict__ in) {
    __shared__ float t[32][33];
    int x0 = blockIdx.x * 32;
    int c0 = blockIdx.y * 32;
    int bh = blockIdx.z;
    int b = bh >> 6, y = bh & 63;
    #pragma unroll
    for (int i = threadIdx.y; i < 32; i += 8)
        t[i][threadIdx.x] = in[(((size_t)(b*Cch + c0 + i)*Hh + y)*Ww) + x0 + threadIdx.x];
    __syncthreads();
    #pragma unroll
    for (int i = threadIdx.y; i < 32; i += 8)
        g_nhwc[(((size_t)(b*Hh + y)*Ww + x0 + i) << 8) + c0 + threadIdx.x] = t[threadIdx.x][i];
}

// ---------------- 2) offset conv ----------------
#define OC_CH 16
__global__ __launch_bounds__(256) void k_offset_conv(const float* __restrict__ in,
                                                     const float* __restrict__ w_off,
                                                     const float* __restrict__ b_off) {
    int bid = blockIdx.x;
    int b = bid >> 6, y = bid & 63;
    int tid = threadIdx.x;
    int x  = tid & 63;
    int jj = tid >> 6;
    __shared__ float sin_[3][OC_CH][66];
    __shared__ float ws[18][OC_CH][9];
    float acc[5] = {0.f, 0.f, 0.f, 0.f, 0.f};

    for (int c0 = 0; c0 < Cch; c0 += OC_CH) {
        for (int idx = tid; idx < 3*OC_CH*66; idx += 256) {
            int r  = idx / (OC_CH*66);
            int rem = idx - r*(OC_CH*66);
            int cc = rem / 66;
            int xx = rem - cc*66;
            int gy = y - 1 + r;
            int gx = xx - 1;
            float v = 0.f;
            if ((unsigned)gy < 64u && (unsigned)gx < 64u)
                v = in[(((size_t)(b*Cch + c0 + cc)*Hh + gy)*Ww) + gx];
            sin_[r][cc][xx] = v;
        }
        for (int idx = tid; idx < 18*OC_CH*9; idx += 256) {
            int j  = idx / (OC_CH*9);
            int rem = idx - j*(OC_CH*9);
            int cc = rem / 9;
            int p  = rem - cc*9;
            ws[j][cc][p] = w_off[((size_t)(j*Cch + c0 + cc))*9 + p];
        }
        __syncthreads();
        for (int cc = 0; cc < OC_CH; cc++) {
            #pragma unroll
            for (int i = 0; i < 3; i++) {
                #pragma unroll
                for (int jx = 0; jx < 3; jx++) {
                    float v = sin_[i][cc][x + jx];
                    int p = i*3 + jx;
                    #pragma unroll
                    for (int t = 0; t < 5; t++) {
                        int j = jj + (t << 2);
                        if (j < 18) acc[t] += v * ws[j][cc][p];
                    }
                }
            }
        }
        __syncthreads();
    }
    #pragma unroll
    for (int t = 0; t < 5; t++) {
        int j = jj + (t << 2);
        if (j < 18)
            g_off[(((size_t)(b*18 + j)*Hh + y)*Ww) + x] = acc[t] + b_off[j];
    }
}

// ---------------- 3) bilinear sample -> bf16 hi/lo im2col ----------------
__global__ __launch_bounds__(64) void k_sample() {
    int m = blockIdx.x;
    int b = m >> 12, y = (m >> 6) & 63, x = m & 63;
    int c = threadIdx.x * 4;

    for (int k = 0; k < Kt; k++) {
        float dy = g_off[(((size_t)(b*18 + 2*k    )*Hh + y)*Ww) + x];
        float dx = g_off[(((size_t)(b*18 + 2*k + 1)*Hh + y)*Ww) + x];
        float py = (float)(y - 1 + (k/3)) + dy;
        float px = (float)(x - 1 + (k%3)) + dx;
        float y0f = floorf(py), x0f = floorf(px);
        float ly = py - y0f, lx = px - x0f;
        int y0 = (int)y0f, x0i = (int)x0f;
        int y1 = y0 + 1,  x1 = x0i + 1;
        float vy0 = (y0  >= 0 && y0  < 64) ? 1.f : 0.f;
        float vy1 = (y1  >= 0 && y1  < 64) ? 1.f : 0.f;
        float vx0 = (x0i >= 0 && x0i < 64) ? 1.f : 0.f;
        float vx1 = (x1  >= 0 && x1  < 64) ? 1.f : 0.f;
        float w00 = (1.f-ly)*(1.f-lx)*vy0*vx0;
        float w01 = (1.f-ly)*lx      *vy0*vx1;
        float w10 = ly      *(1.f-lx)*vy1*vx0;
        float w11 = ly      *lx      *vy1*vx1;
        int y0c = min(max(y0, 0), 63), y1c = min(max(y1, 0), 63);
        int x0c = min(max(x0i,0), 63), x1c = min(max(x1, 0), 63);
        const float* p00 = g_nhwc + (((size_t)(b*Hh + y0c)*Ww + x0c) << 8);
        const float* p01 = g_nhwc + (((size_t)(b*Hh + y0c)*Ww + x1c) << 8);
        const float* p10 = g_nhwc + (((size_t)(b*Hh + y1c)*Ww + x0c) << 8);
        const float* p11 = g_nhwc + (((size_t)(b*Hh + y1c)*Ww + x1c) << 8);
        float4 a00 = *(const float4*)(p00 + c);
        float4 a01 = *(const float4*)(p01 + c);
        float4 a10 = *(const float4*)(p10 + c);
        float4 a11 = *(const float4*)(p11 + c);
        float4 r;
        r.x = w00*a00.x + w01*a01.x + w10*a10.x + w11*a11.x;
        r.y = w00*a00.y + w01*a01.y + w10*a10.y + w11*a11.y;
        r.z = w00*a00.z + w01*a01.z + w10*a10.z + w11*a11.z;
        r.w = w00*a00.w + w01*a01.w + w10*a10.w + w11*a11.w;

        __nv_bfloat162 h01, h23, l01, l23;
        h01.x = __float2bfloat16_rn(r.x); h01.y = __float2bfloat16_rn(r.y);
        h23.x = __float2bfloat16_rn(r.z); h23.y = __float2bfloat16_rn(r.w);
        l01.x = __float2bfloat16_rn(r.x - __bfloat162float(h01.x));
        l01.y = __float2bfloat16_rn(r.y - __bfloat162float(h01.y));
        l23.x = __float2bfloat16_rn(r.z - __bfloat162float(h23.x));
        l23.y = __float2bfloat16_rn(r.w - __bfloat162float(h23.y));
        size_t off = (size_t)m*Kd + k*Cch + c;
        *(__nv_bfloat162*)(g_Ah + off)     = h01;
        *(__nv_bfloat162*)(g_Ah + off + 2) = h23;
        *(__nv_bfloat162*)(g_Al + off)     = l01;
        *(__nv_bfloat162*)(g_Al + off + 2) = l23;
    }
}

// ---------------- 4) weight prep ----------------
__global__ __launch_bounds__(256) void k_prep_weight(const float* __restrict__ w,
                              const float* __restrict__ bias,
                              const float* __restrict__ gamma,
                              const float* __restrict__ beta,
                              const float* __restrict__ mean,
                              const float* __restrict__ var) {
    int o = blockIdx.x;
    int t = threadIdx.x;
    float inv = gamma[o] * rsqrtf(var[o] + 1e-5f);
    for (int kd = t; kd < Kd; kd += 256) {
        int tap = kd >> 8, c = kd & 255;
        float v = w[((size_t)(o*Cch + c))*9 + tap] * inv;
        __nv_bfloat16 hi = __float2bfloat16_rn(v);
        __nv_bfloat16 lo = __float2bfloat16_rn(v - __bfloat162float(hi));
        g_Bh[(size_t)o*Kd + kd] = hi;
        g_Bl[(size_t)o*Kd + kd] = lo;
    }
    if (t == 0)
        g_bias2[o] = bias[o]*inv + beta[o] - mean[o]*inv;
}

// ---------------- 5) bf16 mma.sync GEMM: BM=128, BN=256, single wave ----------------
#define KC 32
#define NCH (Kd/KC)          // 72
#define APL 10240            // A plane bytes (128 rows x 80B)
#define BPL 20480            // B plane bytes (256 rows x 80B)
#define BOFF (2*APL)         // B planes start
#define STG (2*APL + 2*BPL)  // 61440 per stage

__global__ __launch_bounds__(256, 1) void k_gemm_mma(float* __restrict__ out) {
    extern __shared__ char dsm[];
    const uint32_t sbase = smem_u32(dsm);
    const int tid = threadIdx.x, lid = tid & 31, wid = tid >> 5;
    const int warpM = wid & 1, warpN = wid >> 1;   // 2 x 4 -> warp tile 64x64
    const int m0 = blockIdx.x * 128;

    float acc[4][8][4];
    #pragma unroll
    for (int mt = 0; mt < 4; mt++)
        #pragma unroll
        for (int nt = 0; nt < 8; nt++)
            #pragma unroll
            for (int j = 0; j < 4; j++) acc[mt][nt][j] = 0.f;

    // ldmatrix per-thread offsets (within a plane)
    const uint32_t a_off = (uint32_t)((warpM*64 + (lid & 15)) * 80 + (lid >> 4) * 16);
    const uint32_t b_off = (uint32_t)((warpN*64 + (lid & 7) + ((lid >> 4) & 1)*8) * 80
                                      + ((lid >> 3) & 1) * 16);

    auto load = [&](int c, int p) {
        uint32_t sb = sbase + p * STG;
        size_t kOff = (size_t)c * KC;
        // A: 1024 cp.async ops (2 planes x 128 rows x 4 chunks)
        #pragma unroll
        for (int i = 0; i < 4; i++) {
            int idx = tid + i*256;
            int pl = idx >> 9;
            int rr = (idx >> 2) & 127;
            int j  = idx & 3;
            const __nv_bfloat16* src = (pl ? g_Al : g_Ah) + (size_t)(m0 + rr)*Kd + kOff + j*8;
            cpa16(sb + pl*APL + rr*80 + j*16, src);
        }
        // B: 2048 ops (2 planes x 256 rows x 4 chunks)
        #pragma unroll
        for (int i = 0; i < 8; i++) {
            int idx = tid + i*256;
            int pl = idx >> 10;
            int rr = (idx >> 2) & 255;
            int j  = idx & 3;
            const __nv_bfloat16* src = (pl ? g_Bl : g_Bh) + (size_t)rr*Kd + kOff + j*8;
            cpa16(sb + BOFF + pl*BPL + rr*80 + j*16, src);
        }
        asm volatile("cp.async.commit_group;");
    };

    load(0, 0);

    for (int c = 0; c < NCH; c++) {
        int p = c & 1;
        if (c + 1 < NCH) {
            load(c + 1, 1 - p);
            asm volatile("cp.async.wait_group 1;" ::: "memory");
        } else {
            asm volatile("cp.async.wait_group 0;" ::: "memory");
        }
        __syncthreads();

        uint32_t sb = sbase + p * STG;
        #pragma unroll
        for (int kh = 0; kh < 2; kh++) {
            uint32_t ah[4][4], al[4][4];
            #pragma unroll
            for (int mt = 0; mt < 4; mt++) {
                uint32_t addr = sb + a_off + mt*(16*80) + kh*32;
                LDMX4(ah[mt], addr);
                LDMX4(al[mt], addr + APL);
            }
            #pragma unroll
            for (int tp = 0; tp < 4; tp++) {
                uint32_t bh[4], bl[4];
                uint32_t baddr = sb + BOFF + b_off + tp*(16*80) + kh*32;
                LDMX4(bh, baddr);
                LDMX4(bl, baddr + BPL);
                #pragma unroll
                for (int q = 0; q < 2; q++) {
                    int nt = tp*2 + q;
                    #pragma unroll
                    for (int mt = 0; mt < 4; mt++)
                        MMA16816(acc[mt][nt], ah[mt], bh[2*q], bh[2*q+1]);
                    #pragma unroll
                    for (int mt = 0; mt < 4; mt++)
                        MMA16816(acc[mt][nt], ah[mt], bl[2*q], bl[2*q+1]);
                    #pragma unroll
                    for (int mt = 0; mt < 4; mt++)
                        MMA16816(acc[mt][nt], al[mt], bh[2*q], bh[2*q+1]);
                }
            }
        }
        __syncthreads();
    }

    // epilogue: bias + relu, NCHW stores
    #pragma unroll
    for (int mt = 0; mt < 4; mt++) {
        int mA = m0 + warpM*64 + mt*16 + (lid >> 2);
        int mB = mA + 8;
        int bA = mA >> 12, bB = mB >> 12;
        int pA = mA & 4095, pB = mB & 4095;
        #pragma unroll
        for (int nt = 0; nt < 8; nt++) {
            int o = warpN*64 + nt*8 + (lid & 3)*2;
            float bv0 = g_bias2[o], bv1 = g_bias2[o + 1];
            float* d = acc[mt][nt];
            out[((size_t)bA << 20) + ((size_t)o << 12)     + pA] = fmaxf(d[0] + bv0, 0.f);
            out[((size_t)bA << 20) + ((size_t)(o+1) << 12) + pA] = fmaxf(d[1] + bv1, 0.f);
            out[((size_t)bB << 20) + ((size_t)o << 12)     + pB] = fmaxf(d[2] + bv0, 0.f);
            out[((size_t)bB << 20) + ((size_t)(o+1) << 12) + pB] = fmaxf(d[3] + bv1, 0.f);
        }
    }
}

// ---------------- launch ----------------
extern "C" void kernel_launch(void* const* d_in, const int* in_sizes, int n_in,
                              void* d_out, int out_size) {
    const float* input  = (const float*)d_in[0];
    const float* w_off  = (const float*)d_in[1];
    const float* b_off  = (const float*)d_in[2];
    const float* weight = (const float*)d_in[3];
    const float* bias   = (const float*)d_in[4];
    const float* gamma  = (const float*)d_in[5];
    const float* beta   = (const float*)d_in[6];
    const float* mean   = (const float*)d_in[7];
    const float* var    = (const float*)d_in[8];
    float* out = (float*)d_out;

    cudaFuncSetAttribute(k_gemm_mma, cudaFuncAttributeMaxDynamicSharedMemorySize, 2*STG);

    k_transpose<<<dim3(2, 8, Bsz*Hh), dim3(32, 8)>>>(input);
    k_offset_conv<<<Bsz*Hh, 256>>>(input, w_off, b_off);
    k_sample<<<Md, 64>>>();
    k_prep_weight<<<Oo, 256>>>(weight, bias, gamma, beta, mean, var);
    k_gemm_mma<<<Md/128, 256, 2*STG>>>(out);
}

// round 5
// speedup vs baseline: 2.2041x; 1.1759x over previous
#include <cuda_runtime.h>
#include <cuda_fp16.h>
#include <cstdint>

#define Bsz 4
#define Cch 256
#define Hh  64
#define Ww  64
#define Oo  256
#define Kt  9
#define Md  (Bsz*Hh*Ww)   // 16384
#define Kd  (Cch*Kt)      // 2304

// ---------------- scratch ----------------
__device__ float g_nhwc[(size_t)Bsz*Hh*Ww*Cch];
__device__ float g_off[(size_t)Bsz*18*Hh*Ww];
__device__ __half g_Ah[(size_t)Md*Kd];
__device__ __half g_Al[(size_t)Md*Kd];
__device__ __half g_B[(size_t)Oo*Kd];
__device__ float g_bias2[Oo];

// ---------------- helpers ----------------
__device__ __forceinline__ uint32_t smem_u32(const void* p) {
    uint32_t a;
    asm("{ .reg .u64 t; cvta.to.shared.u64 t, %1; cvt.u32.u64 %0, t; }" : "=r"(a) : "l"(p));
    return a;
}
__device__ __forceinline__ void cpa16(uint32_t s, const void* g) {
    asm volatile("cp.async.cg.shared.global [%0], [%1], 16;" :: "r"(s), "l"(g));
}
#define LDMX4(r, addr) \
    asm volatile("ldmatrix.sync.aligned.m8n8.x4.shared.b16 {%0,%1,%2,%3}, [%4];" \
        : "=r"((r)[0]), "=r"((r)[1]), "=r"((r)[2]), "=r"((r)[3]) : "r"(addr))
#define MMA16816(d, a, b0, b1) \
    asm volatile("mma.sync.aligned.m16n8k16.row.col.f32.f16.f16.f32 " \
        "{%0,%1,%2,%3}, {%4,%5,%6,%7}, {%8,%9}, {%0,%1,%2,%3};" \
        : "+f"((d)[0]), "+f"((d)[1]), "+f"((d)[2]), "+f"((d)[3]) \
        : "r"((a)[0]), "r"((a)[1]), "r"((a)[2]), "r"((a)[3]), "r"(b0), "r"(b1))

// ---------------- 1) NCHW -> NHWC transpose + weight prep (fused) ----------------
__global__ void k_transpose_prep(const float* __restrict__ in,
                                 const float* __restrict__ w,
                                 const float* __restrict__ bias,
                                 const float* __restrict__ gamma,
                                 const float* __restrict__ beta,
                                 const float* __restrict__ mean,
                                 const float* __restrict__ var) {
    if (blockIdx.y == 8) {
        // weight prep: o = blockIdx.z, kd half = blockIdx.x
        int o = blockIdx.z;
        int tid = threadIdx.y * 32 + threadIdx.x;
        float inv = gamma[o] * rsqrtf(var[o] + 1e-5f);
        int kd0 = blockIdx.x * (Kd/2);
        for (int i = tid; i < Kd/2; i += 256) {
            int kd = kd0 + i;
            int tap = kd >> 8, c = kd & 255;
            g_B[(size_t)o*Kd + kd] = __float2half_rn(w[((size_t)(o*Cch + c))*9 + tap] * inv);
        }
        if (tid == 0 && blockIdx.x == 0)
            g_bias2[o] = bias[o]*inv + beta[o] - mean[o]*inv;
        return;
    }
    __shared__ float t[32][33];
    int x0 = blockIdx.x * 32;
    int c0 = blockIdx.y * 32;
    int bh = blockIdx.z;
    int b = bh >> 6, y = bh & 63;
    #pragma unroll
    for (int i = threadIdx.y; i < 32; i += 8)
        t[i][threadIdx.x] = in[(((size_t)(b*Cch + c0 + i)*Hh + y)*Ww) + x0 + threadIdx.x];
    __syncthreads();
    #pragma unroll
    for (int i = threadIdx.y; i < 32; i += 8)
        g_nhwc[(((size_t)(b*Hh + y)*Ww + x0 + i) << 8) + c0 + threadIdx.x] = t[threadIdx.x][i];
}

// ---------------- 2) offset conv ----------------
#define OC_CH 16
__global__ __launch_bounds__(256) void k_offset_conv(const float* __restrict__ in,
                                                     const float* __restrict__ w_off,
                                                     const float* __restrict__ b_off) {
    int bid = blockIdx.x;
    int b = bid >> 6, y = bid & 63;
    int tid = threadIdx.x;
    int x  = tid & 63;
    int jj = tid >> 6;
    __shared__ float sin_[3][OC_CH][66];
    __shared__ float ws[18][OC_CH][9];
    float acc[5] = {0.f, 0.f, 0.f, 0.f, 0.f};

    for (int c0 = 0; c0 < Cch; c0 += OC_CH) {
        for (int idx = tid; idx < 3*OC_CH*66; idx += 256) {
            int r  = idx / (OC_CH*66);
            int rem = idx - r*(OC_CH*66);
            int cc = rem / 66;
            int xx = rem - cc*66;
            int gy = y - 1 + r;
            int gx = xx - 1;
            float v = 0.f;
            if ((unsigned)gy < 64u && (unsigned)gx < 64u)
                v = in[(((size_t)(b*Cch + c0 + cc)*Hh + gy)*Ww) + gx];
            sin_[r][cc][xx] = v;
        }
        for (int idx = tid; idx < 18*OC_CH*9; idx += 256) {
            int j  = idx / (OC_CH*9);
            int rem = idx - j*(OC_CH*9);
            int cc = rem / 9;
            int p  = rem - cc*9;
            ws[j][cc][p] = w_off[((size_t)(j*Cch + c0 + cc))*9 + p];
        }
        __syncthreads();
        for (int cc = 0; cc < OC_CH; cc++) {
            #pragma unroll
            for (int i = 0; i < 3; i++) {
                #pragma unroll
                for (int jx = 0; jx < 3; jx++) {
                    float v = sin_[i][cc][x + jx];
                    int p = i*3 + jx;
                    #pragma unroll
                    for (int t = 0; t < 5; t++) {
                        int j = jj + (t << 2);
                        if (j < 18) acc[t] += v * ws[j][cc][p];
                    }
                }
            }
        }
        __syncthreads();
    }
    #pragma unroll
    for (int t = 0; t < 5; t++) {
        int j = jj + (t << 2);
        if (j < 18)
            g_off[(((size_t)(b*18 + j)*Hh + y)*Ww) + x] = acc[t] + b_off[j];
    }
}

// ---------------- 3) bilinear sample -> fp16 hi/lo im2col ----------------
__global__ __launch_bounds__(64) void k_sample() {
    int m = blockIdx.x;
    int b = m >> 12, y = (m >> 6) & 63, x = m & 63;
    int c = threadIdx.x * 4;

    for (int k = 0; k < Kt; k++) {
        float dy = g_off[(((size_t)(b*18 + 2*k    )*Hh + y)*Ww) + x];
        float dx = g_off[(((size_t)(b*18 + 2*k + 1)*Hh + y)*Ww) + x];
        float py = (float)(y - 1 + (k/3)) + dy;
        float px = (float)(x - 1 + (k%3)) + dx;
        float y0f = floorf(py), x0f = floorf(px);
        float ly = py - y0f, lx = px - x0f;
        int y0 = (int)y0f, x0i = (int)x0f;
        int y1 = y0 + 1,  x1 = x0i + 1;
        float vy0 = (y0  >= 0 && y0  < 64) ? 1.f : 0.f;
        float vy1 = (y1  >= 0 && y1  < 64) ? 1.f : 0.f;
        float vx0 = (x0i >= 0 && x0i < 64) ? 1.f : 0.f;
        float vx1 = (x1  >= 0 && x1  < 64) ? 1.f : 0.f;
        float w00 = (1.f-ly)*(1.f-lx)*vy0*vx0;
        float w01 = (1.f-ly)*lx      *vy0*vx1;
        float w10 = ly      *(1.f-lx)*vy1*vx0;
        float w11 = ly      *lx      *vy1*vx1;
        int y0c = min(max(y0, 0), 63), y1c = min(max(y1, 0), 63);
        int x0c = min(max(x0i,0), 63), x1c = min(max(x1, 0), 63);
        const float* p00 = g_nhwc + (((size_t)(b*Hh + y0c)*Ww + x0c) << 8);
        const float* p01 = g_nhwc + (((size_t)(b*Hh + y0c)*Ww + x1c) << 8);
        const float* p10 = g_nhwc + (((size_t)(b*Hh + y1c)*Ww + x0c) << 8);
        const float* p11 = g_nhwc + (((size_t)(b*Hh + y1c)*Ww + x1c) << 8);
        float4 a00 = *(const float4*)(p00 + c);
        float4 a01 = *(const float4*)(p01 + c);
        float4 a10 = *(const float4*)(p10 + c);
        float4 a11 = *(const float4*)(p11 + c);
        float4 r;
        r.x = w00*a00.x + w01*a01.x + w10*a10.x + w11*a11.x;
        r.y = w00*a00.y + w01*a01.y + w10*a10.y + w11*a11.y;
        r.z = w00*a00.z + w01*a01.z + w10*a10.z + w11*a11.z;
        r.w = w00*a00.w + w01*a01.w + w10*a10.w + w11*a11.w;

        __half hx = __float2half_rn(r.x), hy = __float2half_rn(r.y);
        __half hz = __float2half_rn(r.z), hw = __float2half_rn(r.w);
        __half2 h01 = __halves2half2(hx, hy), h23 = __halves2half2(hz, hw);
        __half2 l01 = __halves2half2(__float2half_rn(r.x - __half2float(hx)),
                                     __float2half_rn(r.y - __half2float(hy)));
        __half2 l23 = __halves2half2(__float2half_rn(r.z - __half2float(hz)),
                                     __float2half_rn(r.w - __half2float(hw)));
        size_t off = (size_t)m*Kd + k*Cch + c;
        *(__half2*)(g_Ah + off)     = h01;
        *(__half2*)(g_Ah + off + 2) = h23;
        *(__half2*)(g_Al + off)     = l01;
        *(__half2*)(g_Al + off + 2) = l23;
    }
}

// ---------------- 4) fp16 mma.sync GEMM, 2-term (AhB + AlB), 3-stage pipe ----------------
#define KC 32
#define NCH (Kd/KC)          // 72
#define APL 10240            // A plane (128 rows x 80B)
#define BPL 20480            // B plane (256 rows x 80B)
#define BOFF (2*APL)
#define STG (2*APL + BPL)    // 40960 per stage
#define NSTG 3

__global__ __launch_bounds__(256, 1) void k_gemm_mma(float* __restrict__ out) {
    extern __shared__ char dsm[];
    const uint32_t sbase = smem_u32(dsm);
    const int tid = threadIdx.x, lid = tid & 31, wid = tid >> 5;
    const int warpM = wid & 1, warpN = wid >> 1;   // 2 x 4 -> warp tile 64x64
    const int m0 = blockIdx.x * 128;

    float acc[4][8][4];
    #pragma unroll
    for (int mt = 0; mt < 4; mt++)
        #pragma unroll
        for (int nt = 0; nt < 8; nt++)
            #pragma unroll
            for (int j = 0; j < 4; j++) acc[mt][nt][j] = 0.f;

    const uint32_t a_off = (uint32_t)((warpM*64 + (lid & 15)) * 80 + (lid >> 4) * 16);
    const uint32_t bm_off = (uint32_t)((warpN*64 + (lid & 7) + ((lid >> 4) & 1)*8) * 80
                                       + ((lid >> 3) & 1) * 16);

    auto load = [&](int c, int p) {
        uint32_t sb = sbase + p * STG;
        size_t kOff = (size_t)c * KC;
        // A: 1024 ops (2 planes x 128 rows x 4 x 16B)
        #pragma unroll
        for (int i = 0; i < 4; i++) {
            int idx = tid + i*256;
            int pl = idx >> 9;
            int rr = (idx >> 2) & 127;
            int j  = idx & 3;
            const __half* src = (pl ? g_Al : g_Ah) + (size_t)(m0 + rr)*Kd + kOff + j*8;
            cpa16(sb + pl*APL + rr*80 + j*16, src);
        }
        // B: 1024 ops (256 rows x 4 x 16B)
        #pragma unroll
        for (int i = 0; i < 4; i++) {
            int idx = tid + i*256;
            int rr = idx >> 2;
            int j  = idx & 3;
            const __half* src = g_B + (size_t)rr*Kd + kOff + j*8;
            cpa16(sb + BOFF + rr*80 + j*16, src);
        }
        asm volatile("cp.async.commit_group;");
    };

    load(0, 0);
    load(1, 1);

    for (int c = 0; c < NCH; c++) {
        int p = c % NSTG;
        if (c + 2 < NCH) {
            load(c + 2, (c + 2) % NSTG);
            asm volatile("cp.async.wait_group 2;" ::: "memory");
        } else if (c + 1 < NCH) {
            asm volatile("cp.async.wait_group 1;" ::: "memory");
        } else {
            asm volatile("cp.async.wait_group 0;" ::: "memory");
        }
        __syncthreads();

        uint32_t sb = sbase + p * STG;
        #pragma unroll
        for (int kh = 0; kh < 2; kh++) {
            uint32_t ah[4][4], al[4][4];
            #pragma unroll
            for (int mt = 0; mt < 4; mt++) {
                uint32_t addr = sb + a_off + mt*(16*80) + kh*32;
                LDMX4(ah[mt], addr);
                LDMX4(al[mt], addr + APL);
            }
            #pragma unroll
            for (int tp = 0; tp < 4; tp++) {
                uint32_t bb[4];
                LDMX4(bb, sb + BOFF + bm_off + tp*(16*80) + kh*32);
                #pragma unroll
                for (int q = 0; q < 2; q++) {
                    int nt = tp*2 + q;
                    #pragma unroll
                    for (int mt = 0; mt < 4; mt++)
                        MMA16816(acc[mt][nt], ah[mt], bb[2*q], bb[2*q+1]);
                    #pragma unroll
                    for (int mt = 0; mt < 4; mt++)
                        MMA16816(acc[mt][nt], al[mt], bb[2*q], bb[2*q+1]);
                }
            }
        }
        __syncthreads();
    }

    // epilogue: bias + relu, NCHW stores
    #pragma unroll
    for (int mt = 0; mt < 4; mt++) {
        int mA = m0 + warpM*64 + mt*16 + (lid >> 2);
        int mB = mA + 8;
        int bA = mA >> 12, bB = mB >> 12;
        int pA = mA & 4095, pB = mB & 4095;
        #pragma unroll
        for (int nt = 0; nt < 8; nt++) {
            int o = warpN*64 + nt*8 + (lid & 3)*2;
            float bv0 = g_bias2[o], bv1 = g_bias2[o + 1];
            float* d = acc[mt][nt];
            out[((size_t)bA << 20) + ((size_t)o << 12)     + pA] = fmaxf(d[0] + bv0, 0.f);
            out[((size_t)bA << 20) + ((size_t)(o+1) << 12) + pA] = fmaxf(d[1] + bv1, 0.f);
            out[((size_t)bB << 20) + ((size_t)o << 12)     + pB] = fmaxf(d[2] + bv0, 0.f);
            out[((size_t)bB << 20) + ((size_t)(o+1) << 12) + pB] = fmaxf(d[3] + bv1, 0.f);
        }
    }
}

// ---------------- launch ----------------
extern "C" void kernel_launch(void* const* d_in, const int* in_sizes, int n_in,
                              void* d_out, int out_size) {
    const float* input  = (const float*)d_in[0];
    const float* w_off  = (const float*)d_in[1];
    const float* b_off  = (const float*)d_in[2];
    const float* weight = (const float*)d_in[3];
    const float* bias   = (const float*)d_in[4];
    const float* gamma  = (const float*)d_in[5];
    const float* beta   = (const float*)d_in[6];
    const float* mean   = (const float*)d_in[7];
    const float* var    = (const float*)d_in[8];
    float* out = (float*)d_out;

    cudaFuncSetAttribute(k_gemm_mma, cudaFuncAttributeMaxDynamicSharedMemorySize, NSTG*STG);

    k_transpose_prep<<<dim3(2, 9, Bsz*Hh), dim3(32, 8)>>>(input, weight, bias, gamma, beta, mean, var);
    k_offset_conv<<<Bsz*Hh, 256>>>(input, w_off, b_off);
    k_sample<<<Md, 64>>>();
    k_gemm_mma<<<Md/128, 256, NSTG*STG>>>(out);
}

// round 6
// speedup vs baseline: 2.6028x; 1.1809x over previous
#include <cuda_runtime.h>
#include <cuda_fp16.h>
#include <cstdint>

#define Bsz 4
#define Cch 256
#define Hh  64
#define Ww  64
#define Oo  256
#define Kt  9
#define Md  (Bsz*Hh*Ww)   // 16384
#define Kd  (Cch*Kt)      // 2304

// ---------------- scratch ----------------
__device__ float g_nhwc[(size_t)Bsz*Hh*Ww*Cch];
__device__ float g_off[(size_t)Bsz*18*Hh*Ww];
__device__ __half g_A[(size_t)Md*Kd];
__device__ __half g_B[(size_t)Oo*Kd];
__device__ float g_bias2[Oo];

// ---------------- helpers ----------------
__device__ __forceinline__ uint32_t smem_u32(const void* p) {
    uint32_t a;
    asm("{ .reg .u64 t; cvta.to.shared.u64 t, %1; cvt.u32.u64 %0, t; }" : "=r"(a) : "l"(p));
    return a;
}
__device__ __forceinline__ void cpa16(uint32_t s, const void* g) {
    asm volatile("cp.async.cg.shared.global [%0], [%1], 16;" :: "r"(s), "l"(g));
}
#define LDMX4(r, addr) \
    asm volatile("ldmatrix.sync.aligned.m8n8.x4.shared.b16 {%0,%1,%2,%3}, [%4];" \
        : "=r"((r)[0]), "=r"((r)[1]), "=r"((r)[2]), "=r"((r)[3]) : "r"(addr))
#define MMA16816(d, a, b0, b1) \
    asm volatile("mma.sync.aligned.m16n8k16.row.col.f32.f16.f16.f32 " \
        "{%0,%1,%2,%3}, {%4,%5,%6,%7}, {%8,%9}, {%0,%1,%2,%3};" \
        : "+f"((d)[0]), "+f"((d)[1]), "+f"((d)[2]), "+f"((d)[3]) \
        : "r"((a)[0]), "r"((a)[1]), "r"((a)[2]), "r"((a)[3]), "r"(b0), "r"(b1))

// ---------------- 1) NCHW -> NHWC transpose + weight prep (fused) ----------------
__global__ void k_transpose_prep(const float* __restrict__ in,
                                 const float* __restrict__ w,
                                 const float* __restrict__ bias,
                                 const float* __restrict__ gamma,
                                 const float* __restrict__ beta,
                                 const float* __restrict__ mean,
                                 const float* __restrict__ var) {
    if (blockIdx.y == 8) {
        int o = blockIdx.z;
        int tid = threadIdx.y * 32 + threadIdx.x;
        float inv = gamma[o] * rsqrtf(var[o] + 1e-5f);
        int kd0 = blockIdx.x * (Kd/2);
        for (int i = tid; i < Kd/2; i += 256) {
            int kd = kd0 + i;
            int tap = kd >> 8, c = kd & 255;
            g_B[(size_t)o*Kd + kd] = __float2half_rn(w[((size_t)(o*Cch + c))*9 + tap] * inv);
        }
        if (tid == 0 && blockIdx.x == 0)
            g_bias2[o] = bias[o]*inv + beta[o] - mean[o]*inv;
        return;
    }
    __shared__ float t[32][33];
    int x0 = blockIdx.x * 32;
    int c0 = blockIdx.y * 32;
    int bh = blockIdx.z;
    int b = bh >> 6, y = bh & 63;
    #pragma unroll
    for (int i = threadIdx.y; i < 32; i += 8)
        t[i][threadIdx.x] = in[(((size_t)(b*Cch + c0 + i)*Hh + y)*Ww) + x0 + threadIdx.x];
    __syncthreads();
    #pragma unroll
    for (int i = threadIdx.y; i < 32; i += 8)
        g_nhwc[(((size_t)(b*Hh + y)*Ww + x0 + i) << 8) + c0 + threadIdx.x] = t[threadIdx.x][i];
}

// ---------------- 2) offset conv ----------------
#define OC_CH 16
__global__ __launch_bounds__(256) void k_offset_conv(const float* __restrict__ in,
                                                     const float* __restrict__ w_off,
                                                     const float* __restrict__ b_off) {
    int bid = blockIdx.x;
    int b = bid >> 6, y = bid & 63;
    int tid = threadIdx.x;
    int x  = tid & 63;
    int jj = tid >> 6;
    __shared__ float sin_[3][OC_CH][66];
    __shared__ float ws[18][OC_CH][9];
    float acc[5] = {0.f, 0.f, 0.f, 0.f, 0.f};

    for (int c0 = 0; c0 < Cch; c0 += OC_CH) {
        for (int idx = tid; idx < 3*OC_CH*66; idx += 256) {
            int r  = idx / (OC_CH*66);
            int rem = idx - r*(OC_CH*66);
            int cc = rem / 66;
            int xx = rem - cc*66;
            int gy = y - 1 + r;
            int gx = xx - 1;
            float v = 0.f;
            if ((unsigned)gy < 64u && (unsigned)gx < 64u)
                v = in[(((size_t)(b*Cch + c0 + cc)*Hh + gy)*Ww) + gx];
            sin_[r][cc][xx] = v;
        }
        for (int idx = tid; idx < 18*OC_CH*9; idx += 256) {
            int j  = idx / (OC_CH*9);
            int rem = idx - j*(OC_CH*9);
            int cc = rem / 9;
            int p  = rem - cc*9;
            ws[j][cc][p] = w_off[((size_t)(j*Cch + c0 + cc))*9 + p];
        }
        __syncthreads();
        for (int cc = 0; cc < OC_CH; cc++) {
            #pragma unroll
            for (int i = 0; i < 3; i++) {
                #pragma unroll
                for (int jx = 0; jx < 3; jx++) {
                    float v = sin_[i][cc][x + jx];
                    int p = i*3 + jx;
                    #pragma unroll
                    for (int t = 0; t < 5; t++) {
                        int j = jj + (t << 2);
                        if (j < 18) acc[t] += v * ws[j][cc][p];
                    }
                }
            }
        }
        __syncthreads();
    }
    #pragma unroll
    for (int t = 0; t < 5; t++) {
        int j = jj + (t << 2);
        if (j < 18)
            g_off[(((size_t)(b*18 + j)*Hh + y)*Ww) + x] = acc[t] + b_off[j];
    }
}

// ---------------- 3) bilinear sample -> fp16 im2col (single plane) ----------------
__global__ __launch_bounds__(64) void k_sample() {
    int m = blockIdx.x;
    int b = m >> 12, y = (m >> 6) & 63, x = m & 63;
    int c = threadIdx.x * 4;

    #pragma unroll
    for (int k = 0; k < Kt; k++) {
        float dy = g_off[(((size_t)(b*18 + 2*k    )*Hh + y)*Ww) + x];
        float dx = g_off[(((size_t)(b*18 + 2*k + 1)*Hh + y)*Ww) + x];
        float py = (float)(y - 1 + (k/3)) + dy;
        float px = (float)(x - 1 + (k%3)) + dx;
        float y0f = floorf(py), x0f = floorf(px);
        float ly = py - y0f, lx = px - x0f;
        int y0 = (int)y0f, x0i = (int)x0f;
        int y1 = y0 + 1,  x1 = x0i + 1;
        float vy0 = (y0  >= 0 && y0  < 64) ? 1.f : 0.f;
        float vy1 = (y1  >= 0 && y1  < 64) ? 1.f : 0.f;
        float vx0 = (x0i >= 0 && x0i < 64) ? 1.f : 0.f;
        float vx1 = (x1  >= 0 && x1  < 64) ? 1.f : 0.f;
        float w00 = (1.f-ly)*(1.f-lx)*vy0*vx0;
        float w01 = (1.f-ly)*lx      *vy0*vx1;
        float w10 = ly      *(1.f-lx)*vy1*vx0;
        float w11 = ly      *lx      *vy1*vx1;
        int y0c = min(max(y0, 0), 63), y1c = min(max(y1, 0), 63);
        int x0c = min(max(x0i,0), 63), x1c = min(max(x1, 0), 63);
        const float* p00 = g_nhwc + (((size_t)(b*Hh + y0c)*Ww + x0c) << 8);
        const float* p01 = g_nhwc + (((size_t)(b*Hh + y0c)*Ww + x1c) << 8);
        const float* p10 = g_nhwc + (((size_t)(b*Hh + y1c)*Ww + x0c) << 8);
        const float* p11 = g_nhwc + (((size_t)(b*Hh + y1c)*Ww + x1c) << 8);
        float4 a00 = *(const float4*)(p00 + c);
        float4 a01 = *(const float4*)(p01 + c);
        float4 a10 = *(const float4*)(p10 + c);
        float4 a11 = *(const float4*)(p11 + c);
        float4 r;
        r.x = w00*a00.x + w01*a01.x + w10*a10.x + w11*a11.x;
        r.y = w00*a00.y + w01*a01.y + w10*a10.y + w11*a11.y;
        r.z = w00*a00.z + w01*a01.z + w10*a10.z + w11*a11.z;
        r.w = w00*a00.w + w01*a01.w + w10*a10.w + w11*a11.w;

        __half2 h01 = __halves2half2(__float2half_rn(r.x), __float2half_rn(r.y));
        __half2 h23 = __halves2half2(__float2half_rn(r.z), __float2half_rn(r.w));
        uint2 pk;
        pk.x = *(uint32_t*)&h01;
        pk.y = *(uint32_t*)&h23;
        *(uint2*)(g_A + (size_t)m*Kd + k*Cch + c) = pk;
    }
}

// ---------------- 4) fp16 mma.sync GEMM, 1-term, 4-stage pipe ----------------
#define KC 32
#define NCH (Kd/KC)          // 72
#define APL 10240            // A plane (128 rows x 80B)
#define BPL 20480            // B plane (256 rows x 80B)
#define BOFF APL
#define STG (APL + BPL)      // 30720 per stage
#define NSTG 4

__global__ __launch_bounds__(256, 1) void k_gemm_mma(float* __restrict__ out) {
    extern __shared__ char dsm[];
    const uint32_t sbase = smem_u32(dsm);
    const int tid = threadIdx.x, lid = tid & 31, wid = tid >> 5;
    const int warpM = wid & 1, warpN = wid >> 1;   // 2 x 4 -> warp tile 64x64
    const int m0 = blockIdx.x * 128;

    float acc[4][8][4];
    #pragma unroll
    for (int mt = 0; mt < 4; mt++)
        #pragma unroll
        for (int nt = 0; nt < 8; nt++)
            #pragma unroll
            for (int j = 0; j < 4; j++) acc[mt][nt][j] = 0.f;

    const uint32_t a_off = (uint32_t)((warpM*64 + (lid & 15)) * 80 + (lid >> 4) * 16);
    const uint32_t bm_off = (uint32_t)((warpN*64 + (lid & 7) + ((lid >> 4) & 1)*8) * 80
                                       + ((lid >> 3) & 1) * 16);

    auto load = [&](int c, int p) {
        uint32_t sb = sbase + p * STG;
        size_t kOff = (size_t)c * KC;
        // A: 512 ops (128 rows x 4 x 16B)
        #pragma unroll
        for (int i = 0; i < 2; i++) {
            int idx = tid + i*256;
            int rr = idx >> 2;
            int j  = idx & 3;
            cpa16(sb + rr*80 + j*16, g_A + (size_t)(m0 + rr)*Kd + kOff + j*8);
        }
        // B: 1024 ops (256 rows x 4 x 16B)
        #pragma unroll
        for (int i = 0; i < 4; i++) {
            int idx = tid + i*256;
            int rr = idx >> 2;
            int j  = idx & 3;
            cpa16(sb + BOFF + rr*80 + j*16, g_B + (size_t)rr*Kd + kOff + j*8);
        }
        asm volatile("cp.async.commit_group;");
    };

    load(0, 0);
    load(1, 1);
    load(2, 2);

    for (int c = 0; c < NCH; c++) {
        int p = c & 3;
        if (c + 3 < NCH) {
            load(c + 3, (c + 3) & 3);
            asm volatile("cp.async.wait_group 3;" ::: "memory");
        } else if (c + 2 < NCH) {
            asm volatile("cp.async.wait_group 2;" ::: "memory");
        } else if (c + 1 < NCH) {
            asm volatile("cp.async.wait_group 1;" ::: "memory");
        } else {
            asm volatile("cp.async.wait_group 0;" ::: "memory");
        }
        __syncthreads();

        uint32_t sb = sbase + p * STG;
        #pragma unroll
        for (int kh = 0; kh < 2; kh++) {
            uint32_t ah[4][4];
            #pragma unroll
            for (int mt = 0; mt < 4; mt++)
                LDMX4(ah[mt], sb + a_off + mt*(16*80) + kh*32);
            #pragma unroll
            for (int tp = 0; tp < 4; tp++) {
                uint32_t bb[4];
                LDMX4(bb, sb + BOFF + bm_off + tp*(16*80) + kh*32);
                #pragma unroll
                for (int q = 0; q < 2; q++) {
                    int nt = tp*2 + q;
                    #pragma unroll
                    for (int mt = 0; mt < 4; mt++)
                        MMA16816(acc[mt][nt], ah[mt], bb[2*q], bb[2*q+1]);
                }
            }
        }
        __syncthreads();
    }

    // epilogue: bias + relu, NCHW stores
    #pragma unroll
    for (int mt = 0; mt < 4; mt++) {
        int mA = m0 + warpM*64 + mt*16 + (lid >> 2);
        int mB = mA + 8;
        int bA = mA >> 12, bB = mB >> 12;
        int pA = mA & 4095, pB = mB & 4095;
        #pragma unroll
        for (int nt = 0; nt < 8; nt++) {
            int o = warpN*64 + nt*8 + (lid & 3)*2;
            float bv0 = g_bias2[o], bv1 = g_bias2[o + 1];
            float* d = acc[mt][nt];
            out[((size_t)bA << 20) + ((size_t)o << 12)     + pA] = fmaxf(d[0] + bv0, 0.f);
            out[((size_t)bA << 20) + ((size_t)(o+1) << 12) + pA] = fmaxf(d[1] + bv1, 0.f);
            out[((size_t)bB << 20) + ((size_t)o << 12)     + pB] = fmaxf(d[2] + bv0, 0.f);
            out[((size_t)bB << 20) + ((size_t)(o+1) << 12) + pB] = fmaxf(d[3] + bv1, 0.f);
        }
    }
}

// ---------------- launch ----------------
extern "C" void kernel_launch(void* const* d_in, const int* in_sizes, int n_in,
                              void* d_out, int out_size) {
    const float* input  = (const float*)d_in[0];
    const float* w_off  = (const float*)d_in[1];
    const float* b_off  = (const float*)d_in[2];
    const float* weight = (const float*)d_in[3];
    const float* bias   = (const float*)d_in[4];
    const float* gamma  = (const float*)d_in[5];
    const float* beta   = (const float*)d_in[6];
    const float* mean   = (const float*)d_in[7];
    const float* var    = (const float*)d_in[8];
    float* out = (float*)d_out;

    cudaFuncSetAttribute(k_gemm_mma, cudaFuncAttributeMaxDynamicSharedMemorySize, NSTG*STG);

    k_transpose_prep<<<dim3(2, 9, Bsz*Hh), dim3(32, 8)>>>(input, weight, bias, gamma, beta, mean, var);
    k_offset_conv<<<Bsz*Hh, 256>>>(input, w_off, b_off);
    k_sample<<<Md, 64>>>();
    k_gemm_mma<<<Md/128, 256, NSTG*STG>>>(out);
}